// round 8
// baseline (speedup 1.0000x reference)
#include <cuda_runtime.h>
#include <cuda_bf16.h>
#include <math.h>

// ---------------------------------------------------------------------------
// CrossAttention via bf16x3 split-precision tensor-core GEMMs (mma.sync
// m16n8k16, fp32 accum):  C = Ah*Bh + Ah*Bl + Al*Bh  with x = hi + lo (bf16).
// All GEMM B operands stored [N, K] (k-contiguous): both tiles stage with
// straight cp.async; fragments loaded via ldmatrix (x4 for A, x2 for B).
// Pipeline:
//   decompose(query,key,value) ; transpose-decompose(Wq,Wk,Wv)
//   q = X Wq + bq (bf16 hi/lo)   k = K Wk + bk (bf16 hi/lo)
//   v = V Wv + bv (fp32) -> batched transpose-decompose -> vT hi/lo
//   S = q k^T (fp32) -> softmax -> P hi/lo
//   out = P vT^T (fp32)
// ---------------------------------------------------------------------------

#define BM 128
#define BN 128
#define BKT 32            // bf16 k-tile
#define LDT 40            // smem row stride (bf16): 80B rows -> conflict-free
#define SMEM_ELEMS (4 * 2 * 128 * LDT)
#define SMEM_BYTES (SMEM_ELEMS * 2)           // 81920

// ---------------- scratch ----------------
__device__ __nv_bfloat16 g_qin_h[16777216], g_qin_l[16777216];
__device__ __nv_bfloat16 g_kin_h[8388608],  g_kin_l[8388608];
__device__ __nv_bfloat16 g_vin_h[8388608],  g_vin_l[8388608];
__device__ __nv_bfloat16 g_wqt_h[1048576],  g_wqt_l[1048576];
__device__ __nv_bfloat16 g_wkt_h[524288],   g_wkt_l[524288];
__device__ __nv_bfloat16 g_wvt_h[524288],   g_wvt_l[524288];
__device__ __nv_bfloat16 g_qh[16777216],    g_ql[16777216];
__device__ __nv_bfloat16 g_kh[16777216],    g_kl[16777216];
__device__ float         g_vf[16777216];
__device__ __nv_bfloat16 g_vth[16777216],   g_vtl[16777216];
__device__ float         g_s[33554432];
__device__ __nv_bfloat16 g_ph[33554432],    g_pl[33554432];

// ---------------- helpers ----------------
__device__ __forceinline__ void split2(float x, __nv_bfloat16& h, __nv_bfloat16& l) {
    h = __float2bfloat16(x);
    l = __float2bfloat16(x - __bfloat162float(h));
}
__device__ __forceinline__ void cp_async16(unsigned saddr, const void* g) {
    asm volatile("cp.async.ca.shared.global [%0], [%1], 16;"
                 :: "r"(saddr), "l"(g) : "memory");
}
__device__ __forceinline__ void cp_async_commit() {
    asm volatile("cp.async.commit_group;" ::: "memory");
}
__device__ __forceinline__ void cp_async_wait_all() {
    asm volatile("cp.async.wait_group 0;" ::: "memory");
}
__device__ __forceinline__ void ldsm4(unsigned addr, unsigned r[4]) {
    asm volatile("ldmatrix.sync.aligned.m8n8.x4.shared.b16 {%0,%1,%2,%3}, [%4];"
                 : "=r"(r[0]), "=r"(r[1]), "=r"(r[2]), "=r"(r[3]) : "r"(addr));
}
__device__ __forceinline__ void ldsm2(unsigned addr, unsigned& r0, unsigned& r1) {
    asm volatile("ldmatrix.sync.aligned.m8n8.x2.shared.b16 {%0,%1}, [%2];"
                 : "=r"(r0), "=r"(r1) : "r"(addr));
}
__device__ __forceinline__ void mma_bf16(float c[4], const unsigned a[4],
                                         unsigned b0, unsigned b1) {
    asm volatile(
        "mma.sync.aligned.m16n8k16.row.col.f32.bf16.bf16.f32 "
        "{%0,%1,%2,%3}, {%4,%5,%6,%7}, {%8,%9}, {%0,%1,%2,%3};"
        : "+f"(c[0]), "+f"(c[1]), "+f"(c[2]), "+f"(c[3])
        : "r"(a[0]), "r"(a[1]), "r"(a[2]), "r"(a[3]), "r"(b0), "r"(b1));
}

// ---------------- elementwise decompose: fp32 -> bf16 hi/lo ----------------
__global__ __launch_bounds__(256) void decomp_kernel(
    const float* __restrict__ src, __nv_bfloat16* __restrict__ dh,
    __nv_bfloat16* __restrict__ dl, int n4)
{
    int i = blockIdx.x * 256 + threadIdx.x;
    if (i >= n4) return;
    float4 v = reinterpret_cast<const float4*>(src)[i];
    __nv_bfloat162 h0, h1, l0, l1;
    split2(v.x, h0.x, l0.x); split2(v.y, h0.y, l0.y);
    split2(v.z, h1.x, l1.x); split2(v.w, h1.y, l1.y);
    reinterpret_cast<__nv_bfloat162*>(dh)[i * 2]     = h0;
    reinterpret_cast<__nv_bfloat162*>(dh)[i * 2 + 1] = h1;
    reinterpret_cast<__nv_bfloat162*>(dl)[i * 2]     = l0;
    reinterpret_cast<__nv_bfloat162*>(dl)[i * 2 + 1] = l1;
}

// ------------- transpose + decompose: fp32 [R,C] -> bf16 hi/lo [C,R] -------
__global__ __launch_bounds__(256) void transdecomp_kernel(
    const float* __restrict__ in, __nv_bfloat16* __restrict__ oh,
    __nv_bfloat16* __restrict__ ol, int R, int C,
    long long sIn, long long sOut)
{
    in += (long long)blockIdx.z * sIn;
    oh += (long long)blockIdx.z * sOut;
    ol += (long long)blockIdx.z * sOut;
    __shared__ float tile[32][33];
    const int tx = threadIdx.x, ty = threadIdx.y;      // 32 x 8
    const int c0 = blockIdx.x * 32, r0 = blockIdx.y * 32;
    #pragma unroll
    for (int i = 0; i < 4; i++)
        tile[ty + 8 * i][tx] = in[(long long)(r0 + ty + 8 * i) * C + c0 + tx];
    __syncthreads();
    #pragma unroll
    for (int i = 0; i < 4; i++) {
        float v = tile[tx][ty + 8 * i];
        __nv_bfloat16 h, l;
        split2(v, h, l);
        long long o = (long long)(c0 + ty + 8 * i) * R + r0 + tx;
        oh[o] = h; ol[o] = l;
    }
}

// ---------------- bf16x3 GEMM: C[M,N] = A[M,K] * Bt[N,K]^T (+bias) ----------
template<bool BIAS, bool SPLITOUT>
__global__ __launch_bounds__(256, 2) void gemm_bf16x3(
    const __nv_bfloat16* __restrict__ Ah, const __nv_bfloat16* __restrict__ Al,
    const __nv_bfloat16* __restrict__ Bh, const __nv_bfloat16* __restrict__ Bl,
    const float* __restrict__ bias,
    float* __restrict__ Cf,
    __nv_bfloat16* __restrict__ Ch, __nv_bfloat16* __restrict__ Cl,
    int M, int N, int K, long long sA, long long sB, long long sC)
{
    Ah += (long long)blockIdx.z * sA;  Al += (long long)blockIdx.z * sA;
    Bh += (long long)blockIdx.z * sB;  Bl += (long long)blockIdx.z * sB;
    if (SPLITOUT) { Ch += (long long)blockIdx.z * sC; Cl += (long long)blockIdx.z * sC; }
    else          { Cf += (long long)blockIdx.z * sC; }

    extern __shared__ __nv_bfloat16 smem[];
    __nv_bfloat16* sAh = smem;                 // [2][128][LDT] each region
    __nv_bfloat16* sAl = smem + 10240;
    __nv_bfloat16* sBh = smem + 20480;
    __nv_bfloat16* sBl = smem + 30720;
    const unsigned smem_u = (unsigned)__cvta_generic_to_shared(smem);

    const int tid  = threadIdx.x;
    const int warp = tid >> 5, lane = tid & 31;
    const int wm = warp & 1, wn = warp >> 1;       // 2 x 4 warp grid
    const int g = lane >> 2, t = lane & 3;
    const int lrow = lane & 7, quad = lane >> 3;
    const int row0 = blockIdx.y * BM;
    const int col0 = blockIdx.x * BN;

    // per-lane ldmatrix element offsets (within a buffer)
    const int a_off = (wm * 64 + (quad & 1) * 8 + lrow) * LDT + (quad >> 1) * 8;
    const int b_off = (wn * 32 + lrow) * LDT + (quad & 1) * 8;

    auto stage = [&](int buf, int k0) {
        const int base = buf * 5120;
        #pragma unroll
        for (int l = 0; l < 2; l++) {
            int idx = tid + l * 256;
            int row = idx >> 2, cw = (idx & 3) * 8;
            int so = base + row * LDT + cw;
            long long ga = (long long)(row0 + row) * K + k0 + cw;
            long long gb = (long long)(col0 + row) * K + k0 + cw;
            cp_async16((unsigned)__cvta_generic_to_shared(&sAh[so]), Ah + ga);
            cp_async16((unsigned)__cvta_generic_to_shared(&sAl[so]), Al + ga);
            cp_async16((unsigned)__cvta_generic_to_shared(&sBh[so]), Bh + gb);
            cp_async16((unsigned)__cvta_generic_to_shared(&sBl[so]), Bl + gb);
        }
    };

    float acc[4][4][4];
    #pragma unroll
    for (int i = 0; i < 4; i++)
        #pragma unroll
        for (int j = 0; j < 4; j++)
            #pragma unroll
            for (int e = 0; e < 4; e++) acc[i][j][e] = 0.0f;

    const int nt = K / BKT;
    stage(0, 0);
    cp_async_commit();
    cp_async_wait_all();
    __syncthreads();

    for (int tt = 0; tt < nt; tt++) {
        const int cur = tt & 1;
        if (tt + 1 < nt) { stage(cur ^ 1, (tt + 1) * BKT); cp_async_commit(); }
        const unsigned bufb = smem_u + cur * 10240u;   // byte offset of buffer

        #pragma unroll
        for (int kh = 0; kh < 2; kh++) {
            const int kk = kh * 16;
            unsigned ah[4][4], al[4][4];
            #pragma unroll
            for (int mf = 0; mf < 4; mf++) {
                unsigned aaddr = bufb + 2u * (a_off + mf * 16 * LDT + kk);
                ldsm4(aaddr,          ah[mf]);      // Ah region (+0B)
                ldsm4(aaddr + 20480u, al[mf]);      // Al region
            }
            #pragma unroll
            for (int nf = 0; nf < 4; nf++) {
                unsigned baddr = bufb + 40960u + 2u * (b_off + nf * 8 * LDT + kk);
                unsigned bh0, bh1, bl0, bl1;
                ldsm2(baddr,          bh0, bh1);    // Bh region
                ldsm2(baddr + 20480u, bl0, bl1);    // Bl region
                #pragma unroll
                for (int mf = 0; mf < 4; mf++) {
                    mma_bf16(acc[mf][nf], ah[mf], bh0, bh1);   // hi*hi
                    mma_bf16(acc[mf][nf], ah[mf], bl0, bl1);   // hi*lo
                    mma_bf16(acc[mf][nf], al[mf], bh0, bh1);   // lo*hi
                }
            }
        }
        cp_async_wait_all();
        __syncthreads();
    }

    // epilogue
    #pragma unroll
    for (int mf = 0; mf < 4; mf++) {
        #pragma unroll
        for (int nf = 0; nf < 4; nf++) {
            int rr = row0 + wm * 64 + mf * 16 + g;
            int cc = col0 + wn * 32 + nf * 8 + 2 * t;
            float bx = 0.0f, by = 0.0f;
            if (BIAS) { bx = bias[cc]; by = bias[cc + 1]; }
            #pragma unroll
            for (int h = 0; h < 2; h++) {
                int r = rr + 8 * h;
                float x = acc[mf][nf][2 * h]     + bx;
                float y = acc[mf][nf][2 * h + 1] + by;
                if (SPLITOUT) {
                    __nv_bfloat162 hv, lv;
                    split2(x, hv.x, lv.x); split2(y, hv.y, lv.y);
                    long long o = ((long long)r * N + cc) >> 1;
                    reinterpret_cast<__nv_bfloat162*>(Ch)[o] = hv;
                    reinterpret_cast<__nv_bfloat162*>(Cl)[o] = lv;
                } else {
                    float2 v2; v2.x = x; v2.y = y;
                    *reinterpret_cast<float2*>(&Cf[(long long)r * N + cc]) = v2;
                }
            }
        }
    }
}

// ----- row softmax (len 2048), fp32 in -> bf16 hi/lo out. 1 block/row. -----
__global__ __launch_bounds__(256) void softmax_kernel(
    const float* __restrict__ S, __nv_bfloat16* __restrict__ Ph,
    __nv_bfloat16* __restrict__ Pl)
{
    const float4* row = reinterpret_cast<const float4*>(S) + (long long)blockIdx.x * 512;
    const int tid = threadIdx.x;

    float4 v0 = row[tid];
    float4 v1 = row[tid + 256];

    __shared__ float red[8];

    float m = fmaxf(fmaxf(fmaxf(v0.x, v0.y), fmaxf(v0.z, v0.w)),
                    fmaxf(fmaxf(v1.x, v1.y), fmaxf(v1.z, v1.w)));
    #pragma unroll
    for (int o = 16; o; o >>= 1) m = fmaxf(m, __shfl_xor_sync(0xffffffffu, m, o));
    if ((tid & 31) == 0) red[tid >> 5] = m;
    __syncthreads();
    m = red[0];
    #pragma unroll
    for (int i = 1; i < 8; i++) m = fmaxf(m, red[i]);
    __syncthreads();

    v0.x = expf(v0.x - m); v0.y = expf(v0.y - m);
    v0.z = expf(v0.z - m); v0.w = expf(v0.w - m);
    v1.x = expf(v1.x - m); v1.y = expf(v1.y - m);
    v1.z = expf(v1.z - m); v1.w = expf(v1.w - m);
    float s = (v0.x + v0.y + v0.z + v0.w) + (v1.x + v1.y + v1.z + v1.w);
    #pragma unroll
    for (int o = 16; o; o >>= 1) s += __shfl_xor_sync(0xffffffffu, s, o);
    if ((tid & 31) == 0) red[tid >> 5] = s;
    __syncthreads();
    s = 0.0f;
    #pragma unroll
    for (int i = 0; i < 8; i++) s += red[i];
    const float inv = 1.0f / s;

    long long b2 = (long long)blockIdx.x * 1024;  // bf16x2 units per row
    __nv_bfloat162* H2 = reinterpret_cast<__nv_bfloat162*>(Ph);
    __nv_bfloat162* L2 = reinterpret_cast<__nv_bfloat162*>(Pl);
    __nv_bfloat162 hp, lp;
    split2(v0.x * inv, hp.x, lp.x); split2(v0.y * inv, hp.y, lp.y);
    H2[b2 + tid * 2] = hp; L2[b2 + tid * 2] = lp;
    split2(v0.z * inv, hp.x, lp.x); split2(v0.w * inv, hp.y, lp.y);
    H2[b2 + tid * 2 + 1] = hp; L2[b2 + tid * 2 + 1] = lp;
    split2(v1.x * inv, hp.x, lp.x); split2(v1.y * inv, hp.y, lp.y);
    H2[b2 + (tid + 256) * 2] = hp; L2[b2 + (tid + 256) * 2] = lp;
    split2(v1.z * inv, hp.x, lp.x); split2(v1.w * inv, hp.y, lp.y);
    H2[b2 + (tid + 256) * 2 + 1] = hp; L2[b2 + (tid + 256) * 2 + 1] = lp;
}

extern "C" void kernel_launch(void* const* d_in, const int* in_sizes, int n_in,
                              void* d_out, int out_size)
{
    const float* query = (const float*)d_in[0];  // [8,2048,1024]
    const float* key   = (const float*)d_in[1];  // [8,2048,512]
    const float* value = (const float*)d_in[2];  // [8,2048,512]
    const float* Wq    = (const float*)d_in[3];  // [1024,1024]
    const float* bq    = (const float*)d_in[4];
    const float* Wk    = (const float*)d_in[5];  // [512,1024]
    const float* bk    = (const float*)d_in[6];
    const float* Wv    = (const float*)d_in[7];  // [512,1024]
    const float* bv    = (const float*)d_in[8];
    float* out = (float*)d_out;                  // [8,2048,1024]

    cudaFuncSetAttribute(gemm_bf16x3<true,  true >,
                         cudaFuncAttributeMaxDynamicSharedMemorySize, SMEM_BYTES);
    cudaFuncSetAttribute(gemm_bf16x3<true,  false>,
                         cudaFuncAttributeMaxDynamicSharedMemorySize, SMEM_BYTES);
    cudaFuncSetAttribute(gemm_bf16x3<false, false>,
                         cudaFuncAttributeMaxDynamicSharedMemorySize, SMEM_BYTES);

    __nv_bfloat16 *qin_h, *qin_l, *kin_h, *kin_l, *vin_h, *vin_l;
    __nv_bfloat16 *wqt_h, *wqt_l, *wkt_h, *wkt_l, *wvt_h, *wvt_l;
    __nv_bfloat16 *qh, *ql, *kh, *kl, *vth, *vtl, *ph, *pl;
    float *vf, *sc;
    cudaGetSymbolAddress((void**)&qin_h, g_qin_h); cudaGetSymbolAddress((void**)&qin_l, g_qin_l);
    cudaGetSymbolAddress((void**)&kin_h, g_kin_h); cudaGetSymbolAddress((void**)&kin_l, g_kin_l);
    cudaGetSymbolAddress((void**)&vin_h, g_vin_h); cudaGetSymbolAddress((void**)&vin_l, g_vin_l);
    cudaGetSymbolAddress((void**)&wqt_h, g_wqt_h); cudaGetSymbolAddress((void**)&wqt_l, g_wqt_l);
    cudaGetSymbolAddress((void**)&wkt_h, g_wkt_h); cudaGetSymbolAddress((void**)&wkt_l, g_wkt_l);
    cudaGetSymbolAddress((void**)&wvt_h, g_wvt_h); cudaGetSymbolAddress((void**)&wvt_l, g_wvt_l);
    cudaGetSymbolAddress((void**)&qh, g_qh); cudaGetSymbolAddress((void**)&ql, g_ql);
    cudaGetSymbolAddress((void**)&kh, g_kh); cudaGetSymbolAddress((void**)&kl, g_kl);
    cudaGetSymbolAddress((void**)&vf, g_vf);
    cudaGetSymbolAddress((void**)&vth, g_vth); cudaGetSymbolAddress((void**)&vtl, g_vtl);
    cudaGetSymbolAddress((void**)&sc, g_s);
    cudaGetSymbolAddress((void**)&ph, g_ph); cudaGetSymbolAddress((void**)&pl, g_pl);

    const dim3 blk(256);
    const long long QKV = 2048LL * 1024;
    const long long SS  = 2048LL * 2048;

    // 1) decompose inputs
    decomp_kernel<<<16384, blk>>>(query, qin_h, qin_l, 16777216 / 4);
    decomp_kernel<<<8192,  blk>>>(key,   kin_h, kin_l, 8388608  / 4);
    decomp_kernel<<<8192,  blk>>>(value, vin_h, vin_l, 8388608  / 4);

    // 2) transpose+decompose weights: W[in,out] -> Wt[out,in]
    transdecomp_kernel<<<dim3(32, 32, 1), dim3(32, 8)>>>(Wq, wqt_h, wqt_l, 1024, 1024, 0, 0);
    transdecomp_kernel<<<dim3(32, 16, 1), dim3(32, 8)>>>(Wk, wkt_h, wkt_l, 512,  1024, 0, 0);
    transdecomp_kernel<<<dim3(32, 16, 1), dim3(32, 8)>>>(Wv, wvt_h, wvt_l, 512,  1024, 0, 0);

    // 3) projections
    gemm_bf16x3<true, true ><<<dim3(8, 128, 1), blk, SMEM_BYTES>>>(
        qin_h, qin_l, wqt_h, wqt_l, bq, nullptr, qh, ql, 16384, 1024, 1024, 0, 0, 0);
    gemm_bf16x3<true, true ><<<dim3(8, 128, 1), blk, SMEM_BYTES>>>(
        kin_h, kin_l, wkt_h, wkt_l, bk, nullptr, kh, kl, 16384, 1024, 512, 0, 0, 0);
    gemm_bf16x3<true, false><<<dim3(8, 128, 1), blk, SMEM_BYTES>>>(
        vin_h, vin_l, wvt_h, wvt_l, bv, vf, nullptr, nullptr, 16384, 1024, 512, 0, 0, 0);

    // 4) batched transpose+decompose of v: [2048,1024] -> vT [1024,2048]
    transdecomp_kernel<<<dim3(32, 64, 8), dim3(32, 8)>>>(
        vf, vth, vtl, 2048, 1024, QKV, QKV);

    // 5) scores = q k^T (per batch)
    gemm_bf16x3<false, false><<<dim3(16, 16, 8), blk, SMEM_BYTES>>>(
        qh, ql, kh, kl, nullptr, sc, nullptr, nullptr,
        2048, 2048, 1024, QKV, QKV, SS);

    // 6) softmax -> P hi/lo
    softmax_kernel<<<16384, blk>>>(sc, ph, pl);

    // 7) out = P vT^T (per batch)
    gemm_bf16x3<false, false><<<dim3(8, 16, 8), blk, SMEM_BYTES>>>(
        ph, pl, vth, vtl, nullptr, out, nullptr, nullptr,
        2048, 1024, 2048, SS, QKV, QKV);
}

// round 13
// speedup vs baseline: 1.0034x; 1.0034x over previous
#include <cuda_runtime.h>
#include <cuda_bf16.h>
#include <math.h>

// ---------------------------------------------------------------------------
// CrossAttention via bf16x3 split-precision tensor-core GEMMs (mma.sync
// m16n8k16, fp32 accum):  C = Ah*Bh + Ah*Bl + Al*Bh  with x = hi + lo (bf16).
// NOTE (r12): tcgen05 is NOT available — harness toolchain targets sm_103
// (no 'a' features). This is the legacy-HMMA path, measured 1683.6us at r8.
// r12 changes: term-major inner loop (acc RAW distance 1 -> 4 MMA issues),
// launch order puts q-proj GEMM at launch #6 for ncu (-s 5 -c 1).
// ---------------------------------------------------------------------------

#define BM 128
#define BN 128
#define BKT 32            // bf16 k-tile
#define LDT 40            // smem row stride (bf16): 80B rows -> conflict-free
#define SMEM_ELEMS (4 * 2 * 128 * LDT)
#define SMEM_BYTES (SMEM_ELEMS * 2)           // 81920

// ---------------- scratch ----------------
__device__ __nv_bfloat16 g_qin_h[16777216], g_qin_l[16777216];
__device__ __nv_bfloat16 g_kin_h[8388608],  g_kin_l[8388608];
__device__ __nv_bfloat16 g_vin_h[8388608],  g_vin_l[8388608];
__device__ __nv_bfloat16 g_wqt_h[1048576],  g_wqt_l[1048576];
__device__ __nv_bfloat16 g_wkt_h[524288],   g_wkt_l[524288];
__device__ __nv_bfloat16 g_wvt_h[524288],   g_wvt_l[524288];
__device__ __nv_bfloat16 g_qh[16777216],    g_ql[16777216];
__device__ __nv_bfloat16 g_kh[16777216],    g_kl[16777216];
__device__ float         g_vf[16777216];
__device__ __nv_bfloat16 g_vth[16777216],   g_vtl[16777216];
__device__ float         g_s[33554432];
__device__ __nv_bfloat16 g_ph[33554432],    g_pl[33554432];

// ---------------- helpers ----------------
__device__ __forceinline__ void split2(float x, __nv_bfloat16& h, __nv_bfloat16& l) {
    h = __float2bfloat16(x);
    l = __float2bfloat16(x - __bfloat162float(h));
}
__device__ __forceinline__ void cp_async16(unsigned saddr, const void* g) {
    asm volatile("cp.async.ca.shared.global [%0], [%1], 16;"
                 :: "r"(saddr), "l"(g) : "memory");
}
__device__ __forceinline__ void cp_async_commit() {
    asm volatile("cp.async.commit_group;" ::: "memory");
}
__device__ __forceinline__ void cp_async_wait_all() {
    asm volatile("cp.async.wait_group 0;" ::: "memory");
}
__device__ __forceinline__ void ldsm4(unsigned addr, unsigned r[4]) {
    asm volatile("ldmatrix.sync.aligned.m8n8.x4.shared.b16 {%0,%1,%2,%3}, [%4];"
                 : "=r"(r[0]), "=r"(r[1]), "=r"(r[2]), "=r"(r[3]) : "r"(addr));
}
__device__ __forceinline__ void ldsm2(unsigned addr, unsigned& r0, unsigned& r1) {
    asm volatile("ldmatrix.sync.aligned.m8n8.x2.shared.b16 {%0,%1}, [%2];"
                 : "=r"(r0), "=r"(r1) : "r"(addr));
}
__device__ __forceinline__ void mma_bf16(float c[4], const unsigned a[4],
                                         unsigned b0, unsigned b1) {
    asm volatile(
        "mma.sync.aligned.m16n8k16.row.col.f32.bf16.bf16.f32 "
        "{%0,%1,%2,%3}, {%4,%5,%6,%7}, {%8,%9}, {%0,%1,%2,%3};"
        : "+f"(c[0]), "+f"(c[1]), "+f"(c[2]), "+f"(c[3])
        : "r"(a[0]), "r"(a[1]), "r"(a[2]), "r"(a[3]), "r"(b0), "r"(b1));
}

// ---------------- elementwise decompose: fp32 -> bf16 hi/lo ----------------
__global__ __launch_bounds__(256) void decomp_kernel(
    const float* __restrict__ src, __nv_bfloat16* __restrict__ dh,
    __nv_bfloat16* __restrict__ dl, int n4)
{
    int i = blockIdx.x * 256 + threadIdx.x;
    if (i >= n4) return;
    float4 v = reinterpret_cast<const float4*>(src)[i];
    __nv_bfloat162 h0, h1, l0, l1;
    split2(v.x, h0.x, l0.x); split2(v.y, h0.y, l0.y);
    split2(v.z, h1.x, l1.x); split2(v.w, h1.y, l1.y);
    reinterpret_cast<__nv_bfloat162*>(dh)[i * 2]     = h0;
    reinterpret_cast<__nv_bfloat162*>(dh)[i * 2 + 1] = h1;
    reinterpret_cast<__nv_bfloat162*>(dl)[i * 2]     = l0;
    reinterpret_cast<__nv_bfloat162*>(dl)[i * 2 + 1] = l1;
}

// ------------- transpose + decompose: fp32 [R,C] -> bf16 hi/lo [C,R] -------
__global__ __launch_bounds__(256) void transdecomp_kernel(
    const float* __restrict__ in, __nv_bfloat16* __restrict__ oh,
    __nv_bfloat16* __restrict__ ol, int R, int C,
    long long sIn, long long sOut)
{
    in += (long long)blockIdx.z * sIn;
    oh += (long long)blockIdx.z * sOut;
    ol += (long long)blockIdx.z * sOut;
    __shared__ float tile[32][33];
    const int tx = threadIdx.x, ty = threadIdx.y;      // 32 x 8
    const int c0 = blockIdx.x * 32, r0 = blockIdx.y * 32;
    #pragma unroll
    for (int i = 0; i < 4; i++)
        tile[ty + 8 * i][tx] = in[(long long)(r0 + ty + 8 * i) * C + c0 + tx];
    __syncthreads();
    #pragma unroll
    for (int i = 0; i < 4; i++) {
        float v = tile[tx][ty + 8 * i];
        __nv_bfloat16 h, l;
        split2(v, h, l);
        long long o = (long long)(c0 + ty + 8 * i) * R + r0 + tx;
        oh[o] = h; ol[o] = l;
    }
}

// ---------------- bf16x3 GEMM: C[M,N] = A[M,K] * Bt[N,K]^T (+bias) ----------
template<bool BIAS, bool SPLITOUT>
__global__ __launch_bounds__(256, 2) void gemm_bf16x3(
    const __nv_bfloat16* __restrict__ Ah, const __nv_bfloat16* __restrict__ Al,
    const __nv_bfloat16* __restrict__ Bh, const __nv_bfloat16* __restrict__ Bl,
    const float* __restrict__ bias,
    float* __restrict__ Cf,
    __nv_bfloat16* __restrict__ Ch, __nv_bfloat16* __restrict__ Cl,
    int M, int N, int K, long long sA, long long sB, long long sC)
{
    Ah += (long long)blockIdx.z * sA;  Al += (long long)blockIdx.z * sA;
    Bh += (long long)blockIdx.z * sB;  Bl += (long long)blockIdx.z * sB;
    if (SPLITOUT) { Ch += (long long)blockIdx.z * sC; Cl += (long long)blockIdx.z * sC; }
    else          { Cf += (long long)blockIdx.z * sC; }

    extern __shared__ __nv_bfloat16 smem[];
    __nv_bfloat16* sAh = smem;                 // [2][128][LDT] each region
    __nv_bfloat16* sAl = smem + 10240;
    __nv_bfloat16* sBh = smem + 20480;
    __nv_bfloat16* sBl = smem + 30720;
    const unsigned smem_u = (unsigned)__cvta_generic_to_shared(smem);

    const int tid  = threadIdx.x;
    const int warp = tid >> 5, lane = tid & 31;
    const int wm = warp & 1, wn = warp >> 1;       // 2 x 4 warp grid
    const int g = lane >> 2, t = lane & 3;
    const int lrow = lane & 7, quad = lane >> 3;
    const int row0 = blockIdx.y * BM;
    const int col0 = blockIdx.x * BN;

    // per-lane ldmatrix element offsets (within a buffer)
    const int a_off = (wm * 64 + (quad & 1) * 8 + lrow) * LDT + (quad >> 1) * 8;
    const int b_off = (wn * 32 + lrow) * LDT + (quad & 1) * 8;

    auto stage = [&](int buf, int k0) {
        const int base = buf * 5120;
        #pragma unroll
        for (int l = 0; l < 2; l++) {
            int idx = tid + l * 256;
            int row = idx >> 2, cw = (idx & 3) * 8;
            int so = base + row * LDT + cw;
            long long ga = (long long)(row0 + row) * K + k0 + cw;
            long long gb = (long long)(col0 + row) * K + k0 + cw;
            cp_async16((unsigned)__cvta_generic_to_shared(&sAh[so]), Ah + ga);
            cp_async16((unsigned)__cvta_generic_to_shared(&sAl[so]), Al + ga);
            cp_async16((unsigned)__cvta_generic_to_shared(&sBh[so]), Bh + gb);
            cp_async16((unsigned)__cvta_generic_to_shared(&sBl[so]), Bl + gb);
        }
    };

    float acc[4][4][4];
    #pragma unroll
    for (int i = 0; i < 4; i++)
        #pragma unroll
        for (int j = 0; j < 4; j++)
            #pragma unroll
            for (int e = 0; e < 4; e++) acc[i][j][e] = 0.0f;

    const int nt = K / BKT;
    stage(0, 0);
    cp_async_commit();
    cp_async_wait_all();
    __syncthreads();

    for (int tt = 0; tt < nt; tt++) {
        const int cur = tt & 1;
        if (tt + 1 < nt) { stage(cur ^ 1, (tt + 1) * BKT); cp_async_commit(); }
        const unsigned bufb = smem_u + cur * 10240u;   // byte offset of buffer

        #pragma unroll
        for (int kh = 0; kh < 2; kh++) {
            const int kk = kh * 16;
            unsigned ah[4][4], al[4][4];
            #pragma unroll
            for (int mf = 0; mf < 4; mf++) {
                unsigned aaddr = bufb + 2u * (a_off + mf * 16 * LDT + kk);
                ldsm4(aaddr,          ah[mf]);      // Ah region (+0B)
                ldsm4(aaddr + 20480u, al[mf]);      // Al region
            }
            #pragma unroll
            for (int nf = 0; nf < 4; nf++) {
                unsigned baddr = bufb + 40960u + 2u * (b_off + nf * 8 * LDT + kk);
                unsigned bh0, bh1, bl0, bl1;
                ldsm2(baddr,          bh0, bh1);    // Bh region
                ldsm2(baddr + 20480u, bl0, bl1);    // Bl region
                // term-major: acc reuse distance = 4 MMA issues (was 1)
                #pragma unroll
                for (int mf = 0; mf < 4; mf++)
                    mma_bf16(acc[mf][nf], ah[mf], bh0, bh1);   // hi*hi
                #pragma unroll
                for (int mf = 0; mf < 4; mf++)
                    mma_bf16(acc[mf][nf], ah[mf], bl0, bl1);   // hi*lo
                #pragma unroll
                for (int mf = 0; mf < 4; mf++)
                    mma_bf16(acc[mf][nf], al[mf], bh0, bh1);   // lo*hi
            }
        }
        cp_async_wait_all();
        __syncthreads();
    }

    // epilogue
    #pragma unroll
    for (int mf = 0; mf < 4; mf++) {
        #pragma unroll
        for (int nf = 0; nf < 4; nf++) {
            int rr = row0 + wm * 64 + mf * 16 + g;
            int cc = col0 + wn * 32 + nf * 8 + 2 * t;
            float bx = 0.0f, by = 0.0f;
            if (BIAS) { bx = bias[cc]; by = bias[cc + 1]; }
            #pragma unroll
            for (int h = 0; h < 2; h++) {
                int r = rr + 8 * h;
                float x = acc[mf][nf][2 * h]     + bx;
                float y = acc[mf][nf][2 * h + 1] + by;
                if (SPLITOUT) {
                    __nv_bfloat162 hv, lv;
                    split2(x, hv.x, lv.x); split2(y, hv.y, lv.y);
                    long long o = ((long long)r * N + cc) >> 1;
                    reinterpret_cast<__nv_bfloat162*>(Ch)[o] = hv;
                    reinterpret_cast<__nv_bfloat162*>(Cl)[o] = lv;
                } else {
                    float2 v2; v2.x = x; v2.y = y;
                    *reinterpret_cast<float2*>(&Cf[(long long)r * N + cc]) = v2;
                }
            }
        }
    }
}

// ----- row softmax (len 2048), fp32 in -> bf16 hi/lo out. 1 block/row. -----
__global__ __launch_bounds__(256) void softmax_kernel(
    const float* __restrict__ S, __nv_bfloat16* __restrict__ Ph,
    __nv_bfloat16* __restrict__ Pl)
{
    const float4* row = reinterpret_cast<const float4*>(S) + (long long)blockIdx.x * 512;
    const int tid = threadIdx.x;

    float4 v0 = row[tid];
    float4 v1 = row[tid + 256];

    __shared__ float red[8];

    float m = fmaxf(fmaxf(fmaxf(v0.x, v0.y), fmaxf(v0.z, v0.w)),
                    fmaxf(fmaxf(v1.x, v1.y), fmaxf(v1.z, v1.w)));
    #pragma unroll
    for (int o = 16; o; o >>= 1) m = fmaxf(m, __shfl_xor_sync(0xffffffffu, m, o));
    if ((tid & 31) == 0) red[tid >> 5] = m;
    __syncthreads();
    m = red[0];
    #pragma unroll
    for (int i = 1; i < 8; i++) m = fmaxf(m, red[i]);
    __syncthreads();

    v0.x = expf(v0.x - m); v0.y = expf(v0.y - m);
    v0.z = expf(v0.z - m); v0.w = expf(v0.w - m);
    v1.x = expf(v1.x - m); v1.y = expf(v1.y - m);
    v1.z = expf(v1.z - m); v1.w = expf(v1.w - m);
    float s = (v0.x + v0.y + v0.z + v0.w) + (v1.x + v1.y + v1.z + v1.w);
    #pragma unroll
    for (int o = 16; o; o >>= 1) s += __shfl_xor_sync(0xffffffffu, s, o);
    if ((tid & 31) == 0) red[tid >> 5] = s;
    __syncthreads();
    s = 0.0f;
    #pragma unroll
    for (int i = 0; i < 8; i++) s += red[i];
    const float inv = 1.0f / s;

    long long b2 = (long long)blockIdx.x * 1024;  // bf16x2 units per row
    __nv_bfloat162* H2 = reinterpret_cast<__nv_bfloat162*>(Ph);
    __nv_bfloat162* L2 = reinterpret_cast<__nv_bfloat162*>(Pl);
    __nv_bfloat162 hp, lp;
    split2(v0.x * inv, hp.x, lp.x); split2(v0.y * inv, hp.y, lp.y);
    H2[b2 + tid * 2] = hp; L2[b2 + tid * 2] = lp;
    split2(v0.z * inv, hp.x, lp.x); split2(v0.w * inv, hp.y, lp.y);
    H2[b2 + tid * 2 + 1] = hp; L2[b2 + tid * 2 + 1] = lp;
    split2(v1.x * inv, hp.x, lp.x); split2(v1.y * inv, hp.y, lp.y);
    H2[b2 + (tid + 256) * 2] = hp; L2[b2 + (tid + 256) * 2] = lp;
    split2(v1.z * inv, hp.x, lp.x); split2(v1.w * inv, hp.y, lp.y);
    H2[b2 + (tid + 256) * 2 + 1] = hp; L2[b2 + (tid + 256) * 2 + 1] = lp;
}

extern "C" void kernel_launch(void* const* d_in, const int* in_sizes, int n_in,
                              void* d_out, int out_size)
{
    const float* query = (const float*)d_in[0];  // [8,2048,1024]
    const float* key   = (const float*)d_in[1];  // [8,2048,512]
    const float* value = (const float*)d_in[2];  // [8,2048,512]
    const float* Wq    = (const float*)d_in[3];  // [1024,1024]
    const float* bq    = (const float*)d_in[4];
    const float* Wk    = (const float*)d_in[5];  // [512,1024]
    const float* bk    = (const float*)d_in[6];
    const float* Wv    = (const float*)d_in[7];  // [512,1024]
    const float* bv    = (const float*)d_in[8];
    float* out = (float*)d_out;                  // [8,2048,1024]

    cudaFuncSetAttribute(gemm_bf16x3<true,  true >,
                         cudaFuncAttributeMaxDynamicSharedMemorySize, SMEM_BYTES);
    cudaFuncSetAttribute(gemm_bf16x3<true,  false>,
                         cudaFuncAttributeMaxDynamicSharedMemorySize, SMEM_BYTES);
    cudaFuncSetAttribute(gemm_bf16x3<false, false>,
                         cudaFuncAttributeMaxDynamicSharedMemorySize, SMEM_BYTES);

    __nv_bfloat16 *qin_h, *qin_l, *kin_h, *kin_l, *vin_h, *vin_l;
    __nv_bfloat16 *wqt_h, *wqt_l, *wkt_h, *wkt_l, *wvt_h, *wvt_l;
    __nv_bfloat16 *qh, *ql, *kh, *kl, *vth, *vtl, *ph, *pl;
    float *vf, *sc;
    cudaGetSymbolAddress((void**)&qin_h, g_qin_h); cudaGetSymbolAddress((void**)&qin_l, g_qin_l);
    cudaGetSymbolAddress((void**)&kin_h, g_kin_h); cudaGetSymbolAddress((void**)&kin_l, g_kin_l);
    cudaGetSymbolAddress((void**)&vin_h, g_vin_h); cudaGetSymbolAddress((void**)&vin_l, g_vin_l);
    cudaGetSymbolAddress((void**)&wqt_h, g_wqt_h); cudaGetSymbolAddress((void**)&wqt_l, g_wqt_l);
    cudaGetSymbolAddress((void**)&wkt_h, g_wkt_h); cudaGetSymbolAddress((void**)&wkt_l, g_wkt_l);
    cudaGetSymbolAddress((void**)&wvt_h, g_wvt_h); cudaGetSymbolAddress((void**)&wvt_l, g_wvt_l);
    cudaGetSymbolAddress((void**)&qh, g_qh); cudaGetSymbolAddress((void**)&ql, g_ql);
    cudaGetSymbolAddress((void**)&kh, g_kh); cudaGetSymbolAddress((void**)&kl, g_kl);
    cudaGetSymbolAddress((void**)&vf, g_vf);
    cudaGetSymbolAddress((void**)&vth, g_vth); cudaGetSymbolAddress((void**)&vtl, g_vtl);
    cudaGetSymbolAddress((void**)&sc, g_s);
    cudaGetSymbolAddress((void**)&ph, g_ph); cudaGetSymbolAddress((void**)&pl, g_pl);

    const dim3 blk(256);
    const long long QKV = 2048LL * 1024;
    const long long SS  = 2048LL * 2048;

    // launches ordered so ncu (-s 5 -c 1) captures launch #6 = q-proj GEMM
    transdecomp_kernel<<<dim3(32, 32, 1), dim3(32, 8)>>>(Wq, wqt_h, wqt_l, 1024, 1024, 0, 0);  // 1
    transdecomp_kernel<<<dim3(32, 16, 1), dim3(32, 8)>>>(Wk, wkt_h, wkt_l, 512,  1024, 0, 0);  // 2
    transdecomp_kernel<<<dim3(32, 16, 1), dim3(32, 8)>>>(Wv, wvt_h, wvt_l, 512,  1024, 0, 0);  // 3
    decomp_kernel<<<16384, blk>>>(query, qin_h, qin_l, 16777216 / 4);                          // 4
    decomp_kernel<<<8192,  blk>>>(key,   kin_h, kin_l, 8388608  / 4);                          // 5

    gemm_bf16x3<true, true ><<<dim3(8, 128, 1), blk, SMEM_BYTES>>>(                            // 6
        qin_h, qin_l, wqt_h, wqt_l, bq, nullptr, qh, ql, 16384, 1024, 1024, 0, 0, 0);

    decomp_kernel<<<8192,  blk>>>(value, vin_h, vin_l, 8388608 / 4);                           // 7

    gemm_bf16x3<true, true ><<<dim3(8, 128, 1), blk, SMEM_BYTES>>>(                            // 8
        kin_h, kin_l, wkt_h, wkt_l, bk, nullptr, kh, kl, 16384, 1024, 512, 0, 0, 0);
    gemm_bf16x3<true, false><<<dim3(8, 128, 1), blk, SMEM_BYTES>>>(                            // 9
        vin_h, vin_l, wvt_h, wvt_l, bv, vf, nullptr, nullptr, 16384, 1024, 512, 0, 0, 0);

    transdecomp_kernel<<<dim3(32, 64, 8), dim3(32, 8)>>>(                                      // 10
        vf, vth, vtl, 2048, 1024, QKV, QKV);

    gemm_bf16x3<false, false><<<dim3(16, 16, 8), blk, SMEM_BYTES>>>(                           // 11
        qh, ql, kh, kl, nullptr, sc, nullptr, nullptr,
        2048, 2048, 1024, QKV, QKV, SS);

    softmax_kernel<<<16384, blk>>>(sc, ph, pl);                                                // 12

    gemm_bf16x3<false, false><<<dim3(8, 16, 8), blk, SMEM_BYTES>>>(                            // 13
        ph, pl, vth, vtl, nullptr, out, nullptr, nullptr,
        2048, 1024, 2048, SS, QKV, QKV);
}